// round 16
// baseline (speedup 1.0000x reference)
#include <cuda_runtime.h>
#include <cuda_fp16.h>

#define NN 50000
#define CC 64
#define CH2 128
#define EE 800000
#define NB 49          // ceil(NN/1024)
#define GEPS 1e-7f
#define BNEPS 1e-5f

__device__ __align__(16) int   g_deg[NN];        // zero-init; re-zeroed by k_scanA
__device__ __align__(16) int   g_rowptr[NN + 1]; // block-local exclusive prefixes
__device__ __align__(16) int   g_cursor[NN];     // block-local (scatter adds blkoff)
__device__ __align__(16) int   g_colidx[EE];
__device__ __align__(16) int   g_blk[NB];
__device__ __align__(16) int   g_blkoff[NB];
__device__ int g_ctr;                            // zero-init; reset by last scanA block
__device__ __align__(16) float g_h1[NN * CH2];
__device__ __align__(16) float g_xbuf[NN * CC];
__device__ __align__(16) uint2 g_ep[NN * 32];    // per lane: {half2(E0,E1), half2(P0,P1)}
__device__ __align__(16) float g_stats[2 * 2 * CH2]; // per-layer; zeroed in scanA tail

// ---- packed f32x2 helpers (sm_103a FFMA2) ----
__device__ __forceinline__ unsigned long long pk2(float x, float y) {
    unsigned long long r;
    asm("mov.b64 %0, {%1, %2};" : "=l"(r) : "f"(x), "f"(y));
    return r;
}
__device__ __forceinline__ void upk2(unsigned long long v, float& x, float& y) {
    asm("mov.b64 {%0, %1}, %2;" : "=f"(x), "=f"(y) : "l"(v));
}
__device__ __forceinline__ void ffma2(unsigned long long& d, unsigned long long a,
                                      unsigned long long b) {
    asm("fma.rn.f32x2 %0, %1, %2, %3;" : "=l"(d) : "l"(a), "l"(b), "l"(d));
}

// int64-vs-int32 edge layout probe: int64 (values < 2^31, LE) => odd words zero
__device__ __forceinline__ int detect64(const int* __restrict__ w) {
    int any = 0;
#pragma unroll
    for (int i = 1; i < 128; i += 2) any |= w[i];
    return any == 0;
}

__device__ __forceinline__ uint2 make_ep(float a, float b, float t) {
    float m0 = a + GEPS, m1 = b + GEPS;          // inputs already relu'd
    float e0 = __expf(m0 * t), e1 = __expf(m1 * t);
    uint2 q;
    *(__half2*)&q.x = __floats2half2_rn(e0, e1);
    *(__half2*)&q.y = __floats2half2_rn(m0 * e0, m1 * e1);
    return q;
}

// hist + (E,P) precompute for layer 0 (one float4 per thread covers NN*CC)
__global__ void k_hist(const int* __restrict__ w, const float* __restrict__ x,
                       const float* __restrict__ tp) {
    __shared__ int s64;
    if (threadIdx.x == 0) s64 = detect64(w);
    int e = blockIdx.x * blockDim.x + threadIdx.x;   // 0 .. 800000-1 == NN*CC/4
    {
        float t0 = __ldg(&tp[0]);
        float4 v = ((const float4*)x)[e];
        g_ep[2 * e]     = make_ep(fmaxf(v.x, 0.f), fmaxf(v.y, 0.f), t0);
        g_ep[2 * e + 1] = make_ep(fmaxf(v.z, 0.f), fmaxf(v.w, 0.f), t0);
    }
    __syncthreads();
    if (e < EE) {
        int dstv = s64 ? w[2 * (EE + e)] : w[EE + e];
        atomicAdd(&g_deg[dstv], 1);
    }
}

// per-block scan (+ re-zero g_deg); last block also scans block totals + zeros stats
__global__ void k_scanA() {
    __shared__ int wsum[32];
    __shared__ int islast;
    int tid = threadIdx.x, lane = tid & 31, wid = tid >> 5;
    int i = blockIdx.x * 1024 + tid;
    int v = (i < NN) ? g_deg[i] : 0;
    if (i < NN) g_deg[i] = 0;
    int incl = v;
#pragma unroll
    for (int d = 1; d < 32; d <<= 1) {
        int t = __shfl_up_sync(0xffffffffu, incl, d);
        if (lane >= d) incl += t;
    }
    if (lane == 31) wsum[wid] = incl;
    __syncthreads();
    if (wid == 0) {
        int s = wsum[lane];
        int si = s;
#pragma unroll
        for (int d = 1; d < 32; d <<= 1) {
            int t = __shfl_up_sync(0xffffffffu, si, d);
            if (lane >= d) si += t;
        }
        wsum[lane] = si - s;
        if (lane == 31) g_blk[blockIdx.x] = si;
    }
    __syncthreads();
    if (i < NN) {
        int excl = wsum[wid] + incl - v;
        g_rowptr[i] = excl;
        g_cursor[i] = excl;
        if (i == NN - 1) g_rowptr[NN] = excl + v;
    }
    // last block to finish performs the cross-block scan (fused scanB)
    __threadfence();
    if (tid == 0) islast = (atomicAdd(&g_ctr, 1) == NB - 1);
    __syncthreads();
    if (islast) {
        if (tid < 256) { g_stats[tid] = 0.f; g_stats[256 + tid] = 0.f; }
        if (wid == 0) {
            int a = (lane < NB) ? g_blk[lane] : 0;
            int b = (lane + 32 < NB) ? g_blk[lane + 32] : 0;
            int sa = a, sb = b;
#pragma unroll
            for (int d = 1; d < 32; d <<= 1) {
                int t = __shfl_up_sync(0xffffffffu, sa, d);
                if (lane >= d) sa += t;
                int u = __shfl_up_sync(0xffffffffu, sb, d);
                if (lane >= d) sb += u;
            }
            int T1 = __shfl_sync(0xffffffffu, sa, 31);
            if (lane < NB) g_blkoff[lane] = sa - a;
            if (lane + 32 < NB) g_blkoff[lane + 32] = T1 + sb - b;
            if (lane == 0) g_ctr = 0;   // reset for next graph replay
        }
    }
}

__global__ void k_scatter(const int* __restrict__ w) {
    __shared__ int s64;
    if (threadIdx.x == 0) s64 = detect64(w);
    __syncthreads();
    int e = blockIdx.x * blockDim.x + threadIdx.x;
    if (e < EE) {
        int srcv = s64 ? w[2 * e] : w[e];
        int dstv = s64 ? w[2 * (EE + e)] : w[EE + e];
        int p = atomicAdd(&g_cursor[dstv], 1) + g_blkoff[dstv >> 10];
        g_colidx[p] = srcv;
    }
}

__device__ __forceinline__ void ep_acc(uint2 q, float& den0, float& num0,
                                       float& den1, float& num1) {
    float2 E = __half22float2(*(__half2*)&q.x);
    float2 P = __half22float2(*(__half2*)&q.y);
    den0 += E.x; den1 += E.y;
    num0 += P.x; num1 += P.y;
}

// FUSED: softmax aggregation via precomputed (E,P) gathers (4x unroll, MLP=4)
// -> smem A-tile, then GEMM1 (+bias, BN partial stats). smem 49152B exactly.
__global__ void k_ag1(const float* __restrict__ x_in, int layer,
                      const float* __restrict__ W, const float* __restrict__ bias) {
    extern __shared__ float sm[];
    float* As = sm;               // [64][64] node-major
    float* Bs = sm + 64 * 64;     // [64][128]
    int tid = threadIdx.x;
    int lane = tid & 31, wid = tid >> 5;
    int m0 = blockIdx.x * 64;
    const float* xres = (layer == 0) ? x_in : g_xbuf;   // fp32 residual source

    // stage W while aggregation's gathers are in flight
    for (int i = tid; i < 64 * 32; i += 256)
        ((float4*)Bs)[i] = ((const float4*)W)[i];

#pragma unroll 1
    for (int n = 0; n < 8; n++) {
        int gw = m0 + wid * 8 + n;
        if (gw < NN) {
            int beg = g_rowptr[gw] + g_blkoff[gw >> 10];
            int end = g_rowptr[gw + 1] + g_blkoff[(gw + 1) >> 10];
            float2 xv = ((const float2*)xres)[(size_t)gw * 32 + lane]; // issued early
            float den0 = 0.f, den1 = 0.f, num0 = 0.f, num1 = 0.f;
            float dnA0 = 0.f, dnA1 = 0.f, nmA0 = 0.f, nmA1 = 0.f;     // 2nd acc set
            int i = beg;
            for (; i + 3 < end; i += 4) {                // MLP=4: 4 gathers in flight
                int s0 = g_colidx[i];
                int s1 = g_colidx[i + 1];
                int s2 = g_colidx[i + 2];
                int s3 = g_colidx[i + 3];
                uint2 q0 = g_ep[(size_t)s0 * 32 + lane];
                uint2 q1 = g_ep[(size_t)s1 * 32 + lane];
                uint2 q2 = g_ep[(size_t)s2 * 32 + lane];
                uint2 q3 = g_ep[(size_t)s3 * 32 + lane];
                ep_acc(q0, den0, num0, den1, num1);
                ep_acc(q1, dnA0, nmA0, dnA1, nmA1);
                ep_acc(q2, den0, num0, den1, num1);
                ep_acc(q3, dnA0, nmA0, dnA1, nmA1);
            }
            if (i + 1 < end) {                           // 2-edge remainder
                int s0 = g_colidx[i];
                int s1 = g_colidx[i + 1];
                uint2 q0 = g_ep[(size_t)s0 * 32 + lane];
                uint2 q1 = g_ep[(size_t)s1 * 32 + lane];
                ep_acc(q0, den0, num0, den1, num1);
                ep_acc(q1, dnA0, nmA0, dnA1, nmA1);
                i += 2;
            }
            if (i < end) {
                uint2 q0 = g_ep[(size_t)g_colidx[i] * 32 + lane];
                ep_acc(q0, den0, num0, den1, num1);
            }
            den0 += dnA0; den1 += dnA1; num0 += nmA0; num1 += nmA1;
            float2 o;
            o.x = num0 / (den0 + 1e-16f) + xv.x;
            o.y = num1 / (den1 + 1e-16f) + xv.y;
            *(float2*)(As + (wid * 8 + n) * 64 + 2 * lane) = o;
        }
    }
    __syncthreads();

    int tx = tid & 15, ty = tid >> 4;
    unsigned long long acc[4][4];
#pragma unroll
    for (int r = 0; r < 4; r++)
#pragma unroll
        for (int p = 0; p < 4; p++) acc[r][p] = 0ull;

#pragma unroll 8
    for (int k = 0; k < 64; k++) {
        unsigned long long ar[4];
#pragma unroll
        for (int r = 0; r < 4; r++) {
            float a = As[(ty * 4 + r) * 64 + k];
            ar[r] = pk2(a, a);
        }
#pragma unroll
        for (int p = 0; p < 4; p++) {
            unsigned long long bv =
                *(const unsigned long long*)(Bs + k * CH2 + tx * 2 + p * 32);
#pragma unroll
            for (int r = 0; r < 4; r++) ffma2(acc[r][p], ar[r], bv);
        }
    }
    __syncthreads();   // done reading Bs; reuse as reduction scratch

    float bb[8], ps[8], pq[8];
#pragma unroll
    for (int p = 0; p < 4; p++) {
        int col = tx * 2 + p * 32;
        bb[2 * p] = __ldg(&bias[col]); bb[2 * p + 1] = __ldg(&bias[col + 1]);
        ps[2 * p] = ps[2 * p + 1] = 0.f;
        pq[2 * p] = pq[2 * p + 1] = 0.f;
    }
#pragma unroll
    for (int r = 0; r < 4; r++) {
        int row = m0 + ty * 4 + r;
        if (row < NN) {
#pragma unroll
            for (int p = 0; p < 4; p++) {
                float v0, v1;
                upk2(acc[r][p], v0, v1);
                v0 += bb[2 * p]; v1 += bb[2 * p + 1];
                int col = tx * 2 + p * 32;
                *(float2*)(g_h1 + (size_t)row * CH2 + col) = make_float2(v0, v1);
                ps[2 * p] += v0; pq[2 * p] += v0 * v0;
                ps[2 * p + 1] += v1; pq[2 * p + 1] += v1 * v1;
            }
        }
    }
    float* red = Bs;
#pragma unroll
    for (int p = 0; p < 4; p++) {
        int col = tx * 2 + p * 32;
        red[ty * CH2 + col] = ps[2 * p];
        red[ty * CH2 + col + 1] = ps[2 * p + 1];
        red[2048 + ty * CH2 + col] = pq[2 * p];
        red[2048 + ty * CH2 + col + 1] = pq[2 * p + 1];
    }
    __syncthreads();
    if (tid < CH2) {
        float s1 = 0.f, s2 = 0.f;
#pragma unroll
        for (int j = 0; j < 16; j++) { s1 += red[j * CH2 + tid]; s2 += red[2048 + j * CH2 + tid]; }
        float* st = g_stats + layer * 2 * CH2;
        atomicAdd(&st[tid], s1);
        atomicAdd(&st[CH2 + tid], s2);
    }
}

// GEMM2: out[NN,64] = relu( relu(BN(g_h1)) @ W[128,64] + b )
// layer 0 additionally writes next layer's (E,P) mirror (t = t[1]).
__global__ void k_gemm2(const float* __restrict__ W, const float* __restrict__ bias,
                        const float* __restrict__ gamma, const float* __restrict__ beta,
                        const float* __restrict__ tp, int layer,
                        float* __restrict__ Oout, int to_out) {
    extern __shared__ float sm[];
    float* As = sm;                // [64 rows][128 ch]
    float* Bs = sm + 64 * CH2;     // [64 k][64 cols]
    int tid = threadIdx.x;
    int m0 = blockIdx.x * 64;
    float* O = to_out ? Oout : g_xbuf;
    const float* st = g_stats + layer * 2 * CH2;

    // fill A row-major with BN+ReLU; BN affine derived inline from stats
    const float inv = 1.f / (float)NN;
    for (int i = tid; i < 64 * 32; i += 256) {
        int r = i >> 5, cg = i & 31;
        int c = cg * 4;
        float4 v = make_float4(0.f, 0.f, 0.f, 0.f);
        if (m0 + r < NN) v = *(const float4*)(g_h1 + (size_t)(m0 + r) * CH2 + c);
        float4 s1 = *(const float4*)(st + c);
        float4 s2 = *(const float4*)(st + CH2 + c);
        float4 gg = *(const float4*)(gamma + c);
        float4 bb = *(const float4*)(beta + c);
        float m, sc;
        float4 o;
        m = s1.x * inv; sc = gg.x * rsqrtf(s2.x * inv - m * m + BNEPS);
        o.x = fmaxf(fmaf(v.x, sc, bb.x - m * sc), 0.f);
        m = s1.y * inv; sc = gg.y * rsqrtf(s2.y * inv - m * m + BNEPS);
        o.y = fmaxf(fmaf(v.y, sc, bb.y - m * sc), 0.f);
        m = s1.z * inv; sc = gg.z * rsqrtf(s2.z * inv - m * m + BNEPS);
        o.z = fmaxf(fmaf(v.z, sc, bb.z - m * sc), 0.f);
        m = s1.w * inv; sc = gg.w * rsqrtf(s2.w * inv - m * m + BNEPS);
        o.w = fmaxf(fmaf(v.w, sc, bb.w - m * sc), 0.f);
        *(float4*)(As + r * CH2 + c) = o;
    }

    int tx = tid & 15, ty = tid >> 4;
    unsigned long long acc[4][2];
#pragma unroll
    for (int r = 0; r < 4; r++) { acc[r][0] = 0ull; acc[r][1] = 0ull; }

#pragma unroll 1
    for (int h = 0; h < 2; h++) {
        __syncthreads();   // protects Bs reuse across passes (and A fill on h=0)
        for (int i = tid; i < 64 * 16; i += 256)
            ((float4*)Bs)[i] = ((const float4*)W)[h * 64 * 16 + i];
        __syncthreads();
#pragma unroll 8
        for (int kk = 0; kk < 64; kk++) {
            int k = h * 64 + kk;
            unsigned long long ar[4];
#pragma unroll
            for (int r = 0; r < 4; r++) {
                float a = As[(ty * 4 + r) * CH2 + k];
                ar[r] = pk2(a, a);
            }
            unsigned long long b0 = *(const unsigned long long*)(Bs + kk * CC + tx * 2);
            unsigned long long b1 = *(const unsigned long long*)(Bs + kk * CC + tx * 2 + 32);
#pragma unroll
            for (int r = 0; r < 4; r++) {
                ffma2(acc[r][0], ar[r], b0);
                ffma2(acc[r][1], ar[r], b1);
            }
        }
    }
    float t1 = __ldg(&tp[1]);
#pragma unroll
    for (int r = 0; r < 4; r++) {
        int row = m0 + ty * 4 + r;
        if (row < NN) {
#pragma unroll
            for (int p = 0; p < 2; p++) {
                int col = tx * 2 + p * 32;
                float v0, v1;
                upk2(acc[r][p], v0, v1);
                v0 = fmaxf(v0 + __ldg(&bias[col]), 0.f);
                v1 = fmaxf(v1 + __ldg(&bias[col + 1]), 0.f);
                *(float2*)(O + (size_t)row * CC + col) = make_float2(v0, v1);
                if (!to_out)
                    g_ep[(size_t)row * 32 + col / 2] = make_ep(v0, v1, t1);
            }
        }
    }
}

extern "C" void kernel_launch(void* const* d_in, const int* in_sizes, int n_in,
                              void* d_out, int out_size) {
    const float* x  = (const float*)d_in[0];
    const int*   ei = (const int*)d_in[1];     // int32 or int64 (auto-detected)
    const float* W1 = (const float*)d_in[2];
    const float* b1 = (const float*)d_in[3];
    const float* gm = (const float*)d_in[4];
    const float* bt = (const float*)d_in[5];
    const float* W2 = (const float*)d_in[6];
    const float* b2 = (const float*)d_in[7];
    const float* tt = (const float*)d_in[8];
    float* out = (float*)d_out;

    const int smem1 = (64 * 64 + 64 * 128) * 4;     // 49152 B
    const int smem2 = (64 * 128 + 64 * 64) * 4;     // 49152 B

    // CSR build (recomputed every call; edge_index is an input)
    k_hist<<<(EE + 255) / 256, 256>>>(ei, x, tt);
    k_scanA<<<NB, 1024>>>();
    k_scatter<<<(EE + 255) / 256, 256>>>(ei);

    for (int l = 0; l < 2; l++) {
        k_ag1<<<(NN + 63) / 64, 256, smem1>>>(x, l, W1 + (size_t)l * CC * CH2,
                                              b1 + l * CH2);
        k_gemm2<<<(NN + 63) / 64, 256, smem2>>>(W2 + (size_t)l * CH2 * CC, b2 + l * CC,
                                                gm + l * CH2, bt + l * CH2, tt, l,
                                                out, l == 1);
    }
}

// round 17
// speedup vs baseline: 1.1081x; 1.1081x over previous
#include <cuda_runtime.h>
#include <cuda_fp16.h>

#define NN 50000
#define CC 64
#define CH2 128
#define EE 800000
#define NB 49          // ceil(NN/1024)
#define GEPS 1e-7f
#define BNEPS 1e-5f

__device__ __align__(16) int   g_deg[NN];        // zero-init; re-zeroed by k_scanA
__device__ __align__(16) int   g_rowptr[NN + 1]; // block-local exclusive prefixes
__device__ __align__(16) int   g_cursor[NN];     // block-local (scatter adds blkoff)
__device__ __align__(16) int   g_colidx[EE];
__device__ __align__(16) int   g_blk[NB];
__device__ __align__(16) int   g_blkoff[NB];
__device__ int g_ctr;                            // zero-init; reset by last scanA block
__device__ __align__(16) float g_h0[NN * CC];
__device__ __align__(16) float g_h1[NN * CH2];
__device__ __align__(16) float g_xbuf[NN * CC];
__device__ __align__(16) uint2 g_ep[NN * 32];    // per lane: {half2(E0,E1), half2(P0,P1)}
__device__ __align__(16) float g_stats[2 * 2 * CH2]; // per-layer; zeroed in scanA tail

// ---- packed f32x2 helpers (sm_103a FFMA2) ----
__device__ __forceinline__ unsigned long long pk2(float x, float y) {
    unsigned long long r;
    asm("mov.b64 %0, {%1, %2};" : "=l"(r) : "f"(x), "f"(y));
    return r;
}
__device__ __forceinline__ void upk2(unsigned long long v, float& x, float& y) {
    asm("mov.b64 {%0, %1}, %2;" : "=f"(x), "=f"(y) : "l"(v));
}
__device__ __forceinline__ void ffma2(unsigned long long& d, unsigned long long a,
                                      unsigned long long b) {
    asm("fma.rn.f32x2 %0, %1, %2, %3;" : "=l"(d) : "l"(a), "l"(b), "l"(d));
}

// int64-vs-int32 edge layout probe: int64 (values < 2^31, LE) => odd words zero
__device__ __forceinline__ int detect64(const int* __restrict__ w) {
    int any = 0;
#pragma unroll
    for (int i = 1; i < 128; i += 2) any |= w[i];
    return any == 0;
}

__device__ __forceinline__ uint2 make_ep(float a, float b, float t) {
    float m0 = a + GEPS, m1 = b + GEPS;          // inputs already relu'd
    float e0 = __expf(m0 * t), e1 = __expf(m1 * t);
    uint2 q;
    *(__half2*)&q.x = __floats2half2_rn(e0, e1);
    *(__half2*)&q.y = __floats2half2_rn(m0 * e0, m1 * e1);
    return q;
}

// hist + (E,P) precompute for layer 0 (one float4 per thread covers NN*CC)
__global__ void k_hist(const int* __restrict__ w, const float* __restrict__ x,
                       const float* __restrict__ tp) {
    __shared__ int s64;
    if (threadIdx.x == 0) s64 = detect64(w);
    int e = blockIdx.x * blockDim.x + threadIdx.x;   // 0 .. 800000-1 == NN*CC/4
    {
        float t0 = __ldg(&tp[0]);
        float4 v = ((const float4*)x)[e];
        g_ep[2 * e]     = make_ep(fmaxf(v.x, 0.f), fmaxf(v.y, 0.f), t0);
        g_ep[2 * e + 1] = make_ep(fmaxf(v.z, 0.f), fmaxf(v.w, 0.f), t0);
    }
    __syncthreads();
    if (e < EE) {
        int dstv = s64 ? w[2 * (EE + e)] : w[EE + e];
        atomicAdd(&g_deg[dstv], 1);
    }
}

// per-block scan (+ re-zero g_deg); last block also scans block totals + zeros stats
__global__ void k_scanA() {
    __shared__ int wsum[32];
    __shared__ int islast;
    int tid = threadIdx.x, lane = tid & 31, wid = tid >> 5;
    int i = blockIdx.x * 1024 + tid;
    int v = (i < NN) ? g_deg[i] : 0;
    if (i < NN) g_deg[i] = 0;
    int incl = v;
#pragma unroll
    for (int d = 1; d < 32; d <<= 1) {
        int t = __shfl_up_sync(0xffffffffu, incl, d);
        if (lane >= d) incl += t;
    }
    if (lane == 31) wsum[wid] = incl;
    __syncthreads();
    if (wid == 0) {
        int s = wsum[lane];
        int si = s;
#pragma unroll
        for (int d = 1; d < 32; d <<= 1) {
            int t = __shfl_up_sync(0xffffffffu, si, d);
            if (lane >= d) si += t;
        }
        wsum[lane] = si - s;
        if (lane == 31) g_blk[blockIdx.x] = si;
    }
    __syncthreads();
    if (i < NN) {
        int excl = wsum[wid] + incl - v;
        g_rowptr[i] = excl;
        g_cursor[i] = excl;
        if (i == NN - 1) g_rowptr[NN] = excl + v;
    }
    __threadfence();
    if (tid == 0) islast = (atomicAdd(&g_ctr, 1) == NB - 1);
    __syncthreads();
    if (islast) {
        if (tid < 256) { g_stats[tid] = 0.f; g_stats[256 + tid] = 0.f; }
        if (wid == 0) {
            int a = (lane < NB) ? g_blk[lane] : 0;
            int b = (lane + 32 < NB) ? g_blk[lane + 32] : 0;
            int sa = a, sb = b;
#pragma unroll
            for (int d = 1; d < 32; d <<= 1) {
                int t = __shfl_up_sync(0xffffffffu, sa, d);
                if (lane >= d) sa += t;
                int u = __shfl_up_sync(0xffffffffu, sb, d);
                if (lane >= d) sb += u;
            }
            int T1 = __shfl_sync(0xffffffffu, sa, 31);
            if (lane < NB) g_blkoff[lane] = sa - a;
            if (lane + 32 < NB) g_blkoff[lane + 32] = T1 + sb - b;
            if (lane == 0) g_ctr = 0;   // reset for next graph replay
        }
    }
}

__global__ void k_scatter(const int* __restrict__ w) {
    __shared__ int s64;
    if (threadIdx.x == 0) s64 = detect64(w);
    __syncthreads();
    int e = blockIdx.x * blockDim.x + threadIdx.x;
    if (e < EE) {
        int srcv = s64 ? w[2 * e] : w[e];
        int dstv = s64 ? w[2 * (EE + e)] : w[EE + e];
        int p = atomicAdd(&g_cursor[dstv], 1) + g_blkoff[dstv >> 10];
        g_colidx[p] = srcv;
    }
}

__device__ __forceinline__ void ep_acc(uint2 q, float& den0, float& num0,
                                       float& den1, float& num1) {
    float2 E = __half22float2(*(__half2*)&q.x);
    float2 P = __half22float2(*(__half2*)&q.y);
    den0 += E.x; den1 += E.y;
    num0 += P.x; num1 += P.y;
}

// STANDALONE softmax aggregation: warp-per-node, zero smem -> full occupancy.
// g_h0 = segsum(P)/segsum(E) + xres. No per-edge exp (E,P precomputed).
__global__ void k_aggr(const float* __restrict__ x_in, int layer) {
    int gw = (blockIdx.x * blockDim.x + threadIdx.x) >> 5;
    int lane = threadIdx.x & 31;
    if (gw >= NN) return;
    const float* xres = (layer == 0) ? x_in : g_xbuf;
    int beg = g_rowptr[gw] + g_blkoff[gw >> 10];
    int end = g_rowptr[gw + 1] + g_blkoff[(gw + 1) >> 10];
    float2 xv = ((const float2*)xres)[(size_t)gw * 32 + lane]; // issued early
    float den0 = 0.f, den1 = 0.f, num0 = 0.f, num1 = 0.f;
    float dnA0 = 0.f, dnA1 = 0.f, nmA0 = 0.f, nmA1 = 0.f;
    int i = beg;
    for (; i + 3 < end; i += 4) {                // 4 gathers in flight
        int s0 = g_colidx[i];
        int s1 = g_colidx[i + 1];
        int s2 = g_colidx[i + 2];
        int s3 = g_colidx[i + 3];
        uint2 q0 = g_ep[(size_t)s0 * 32 + lane];
        uint2 q1 = g_ep[(size_t)s1 * 32 + lane];
        uint2 q2 = g_ep[(size_t)s2 * 32 + lane];
        uint2 q3 = g_ep[(size_t)s3 * 32 + lane];
        ep_acc(q0, den0, num0, den1, num1);
        ep_acc(q1, dnA0, nmA0, dnA1, nmA1);
        ep_acc(q2, den0, num0, den1, num1);
        ep_acc(q3, dnA0, nmA0, dnA1, nmA1);
    }
    if (i + 1 < end) {
        int s0 = g_colidx[i];
        int s1 = g_colidx[i + 1];
        uint2 q0 = g_ep[(size_t)s0 * 32 + lane];
        uint2 q1 = g_ep[(size_t)s1 * 32 + lane];
        ep_acc(q0, den0, num0, den1, num1);
        ep_acc(q1, dnA0, nmA0, dnA1, nmA1);
        i += 2;
    }
    if (i < end) {
        uint2 q0 = g_ep[(size_t)g_colidx[i] * 32 + lane];
        ep_acc(q0, den0, num0, den1, num1);
    }
    den0 += dnA0; den1 += dnA1; num0 += nmA0; num1 += nmA1;
    float2 o;
    o.x = num0 / (den0 + 1e-16f) + xv.x;
    o.y = num1 / (den1 + 1e-16f) + xv.y;
    ((float2*)g_h0)[(size_t)gw * 32 + lane] = o;
}

// GEMM1: g_h1[NN,128] = g_h0[NN,64] @ W[64,128] + b ; fused BN partial stats
__global__ void k_gemm1(const float* __restrict__ W, const float* __restrict__ bias,
                        int layer) {
    extern __shared__ float sm[];
    float* As = sm;               // [64][64] node-major
    float* Bs = sm + 64 * 64;     // [64][128]
    int tid = threadIdx.x;
    int m0 = blockIdx.x * 64;

    for (int i = tid; i < 64 * 16; i += 256) {
        int r = i >> 4, c = (i & 15) << 2;
        float4 v = make_float4(0.f, 0.f, 0.f, 0.f);
        if (m0 + r < NN) v = *(const float4*)(g_h0 + (size_t)(m0 + r) * CC + c);
        *(float4*)(As + r * 64 + c) = v;
    }
    for (int i = tid; i < 64 * 32; i += 256)
        ((float4*)Bs)[i] = ((const float4*)W)[i];
    __syncthreads();

    int tx = tid & 15, ty = tid >> 4;
    unsigned long long acc[4][4];
#pragma unroll
    for (int r = 0; r < 4; r++)
#pragma unroll
        for (int p = 0; p < 4; p++) acc[r][p] = 0ull;

#pragma unroll 8
    for (int k = 0; k < 64; k++) {
        unsigned long long ar[4];
#pragma unroll
        for (int r = 0; r < 4; r++) {
            float a = As[(ty * 4 + r) * 64 + k];
            ar[r] = pk2(a, a);
        }
#pragma unroll
        for (int p = 0; p < 4; p++) {
            unsigned long long bv =
                *(const unsigned long long*)(Bs + k * CH2 + tx * 2 + p * 32);
#pragma unroll
            for (int r = 0; r < 4; r++) ffma2(acc[r][p], ar[r], bv);
        }
    }
    __syncthreads();   // done reading Bs; reuse as reduction scratch

    float bb[8], ps[8], pq[8];
#pragma unroll
    for (int p = 0; p < 4; p++) {
        int col = tx * 2 + p * 32;
        bb[2 * p] = __ldg(&bias[col]); bb[2 * p + 1] = __ldg(&bias[col + 1]);
        ps[2 * p] = ps[2 * p + 1] = 0.f;
        pq[2 * p] = pq[2 * p + 1] = 0.f;
    }
#pragma unroll
    for (int r = 0; r < 4; r++) {
        int row = m0 + ty * 4 + r;
        if (row < NN) {
#pragma unroll
            for (int p = 0; p < 4; p++) {
                float v0, v1;
                upk2(acc[r][p], v0, v1);
                v0 += bb[2 * p]; v1 += bb[2 * p + 1];
                int col = tx * 2 + p * 32;
                *(float2*)(g_h1 + (size_t)row * CH2 + col) = make_float2(v0, v1);
                ps[2 * p] += v0; pq[2 * p] += v0 * v0;
                ps[2 * p + 1] += v1; pq[2 * p + 1] += v1 * v1;
            }
        }
    }
    float* red = Bs;
#pragma unroll
    for (int p = 0; p < 4; p++) {
        int col = tx * 2 + p * 32;
        red[ty * CH2 + col] = ps[2 * p];
        red[ty * CH2 + col + 1] = ps[2 * p + 1];
        red[2048 + ty * CH2 + col] = pq[2 * p];
        red[2048 + ty * CH2 + col + 1] = pq[2 * p + 1];
    }
    __syncthreads();
    if (tid < CH2) {
        float s1 = 0.f, s2 = 0.f;
#pragma unroll
        for (int j = 0; j < 16; j++) { s1 += red[j * CH2 + tid]; s2 += red[2048 + j * CH2 + tid]; }
        float* st = g_stats + layer * 2 * CH2;
        atomicAdd(&st[tid], s1);
        atomicAdd(&st[CH2 + tid], s2);
    }
}

// GEMM2: out[NN,64] = relu( relu(BN(g_h1)) @ W[128,64] + b )
// layer 0 additionally writes next layer's (E,P) mirror (t = t[1]).
__global__ void k_gemm2(const float* __restrict__ W, const float* __restrict__ bias,
                        const float* __restrict__ gamma, const float* __restrict__ beta,
                        const float* __restrict__ tp, int layer,
                        float* __restrict__ Oout, int to_out) {
    extern __shared__ float sm[];
    float* As = sm;                // [64 rows][128 ch]
    float* Bs = sm + 64 * CH2;     // [64 k][64 cols]
    int tid = threadIdx.x;
    int m0 = blockIdx.x * 64;
    float* O = to_out ? Oout : g_xbuf;
    const float* st = g_stats + layer * 2 * CH2;

    const float inv = 1.f / (float)NN;
    for (int i = tid; i < 64 * 32; i += 256) {
        int r = i >> 5, cg = i & 31;
        int c = cg * 4;
        float4 v = make_float4(0.f, 0.f, 0.f, 0.f);
        if (m0 + r < NN) v = *(const float4*)(g_h1 + (size_t)(m0 + r) * CH2 + c);
        float4 s1 = *(const float4*)(st + c);
        float4 s2 = *(const float4*)(st + CH2 + c);
        float4 gg = *(const float4*)(gamma + c);
        float4 bb = *(const float4*)(beta + c);
        float m, sc;
        float4 o;
        m = s1.x * inv; sc = gg.x * rsqrtf(s2.x * inv - m * m + BNEPS);
        o.x = fmaxf(fmaf(v.x, sc, bb.x - m * sc), 0.f);
        m = s1.y * inv; sc = gg.y * rsqrtf(s2.y * inv - m * m + BNEPS);
        o.y = fmaxf(fmaf(v.y, sc, bb.y - m * sc), 0.f);
        m = s1.z * inv; sc = gg.z * rsqrtf(s2.z * inv - m * m + BNEPS);
        o.z = fmaxf(fmaf(v.z, sc, bb.z - m * sc), 0.f);
        m = s1.w * inv; sc = gg.w * rsqrtf(s2.w * inv - m * m + BNEPS);
        o.w = fmaxf(fmaf(v.w, sc, bb.w - m * sc), 0.f);
        *(float4*)(As + r * CH2 + c) = o;
    }

    int tx = tid & 15, ty = tid >> 4;
    unsigned long long acc[4][2];
#pragma unroll
    for (int r = 0; r < 4; r++) { acc[r][0] = 0ull; acc[r][1] = 0ull; }

#pragma unroll 1
    for (int h = 0; h < 2; h++) {
        __syncthreads();   // protects Bs reuse across passes (and A fill on h=0)
        for (int i = tid; i < 64 * 16; i += 256)
            ((float4*)Bs)[i] = ((const float4*)W)[h * 64 * 16 + i];
        __syncthreads();
#pragma unroll 8
        for (int kk = 0; kk < 64; kk++) {
            int k = h * 64 + kk;
            unsigned long long ar[4];
#pragma unroll
            for (int r = 0; r < 4; r++) {
                float a = As[(ty * 4 + r) * CH2 + k];
                ar[r] = pk2(a, a);
            }
            unsigned long long b0 = *(const unsigned long long*)(Bs + kk * CC + tx * 2);
            unsigned long long b1 = *(const unsigned long long*)(Bs + kk * CC + tx * 2 + 32);
#pragma unroll
            for (int r = 0; r < 4; r++) {
                ffma2(acc[r][0], ar[r], b0);
                ffma2(acc[r][1], ar[r], b1);
            }
        }
    }
    float t1 = __ldg(&tp[1]);
#pragma unroll
    for (int r = 0; r < 4; r++) {
        int row = m0 + ty * 4 + r;
        if (row < NN) {
#pragma unroll
            for (int p = 0; p < 2; p++) {
                int col = tx * 2 + p * 32;
                float v0, v1;
                upk2(acc[r][p], v0, v1);
                v0 = fmaxf(v0 + __ldg(&bias[col]), 0.f);
                v1 = fmaxf(v1 + __ldg(&bias[col + 1]), 0.f);
                *(float2*)(O + (size_t)row * CC + col) = make_float2(v0, v1);
                if (!to_out)
                    g_ep[(size_t)row * 32 + col / 2] = make_ep(v0, v1, t1);
            }
        }
    }
}

extern "C" void kernel_launch(void* const* d_in, const int* in_sizes, int n_in,
                              void* d_out, int out_size) {
    const float* x  = (const float*)d_in[0];
    const int*   ei = (const int*)d_in[1];     // int32 or int64 (auto-detected)
    const float* W1 = (const float*)d_in[2];
    const float* b1 = (const float*)d_in[3];
    const float* gm = (const float*)d_in[4];
    const float* bt = (const float*)d_in[5];
    const float* W2 = (const float*)d_in[6];
    const float* b2 = (const float*)d_in[7];
    const float* tt = (const float*)d_in[8];
    float* out = (float*)d_out;

    const int smem1 = (64 * 64 + 64 * 128) * 4;     // 49152 B
    const int smem2 = (64 * 128 + 64 * 64) * 4;     // 49152 B

    // CSR build (recomputed every call; edge_index is an input)
    k_hist<<<(EE + 255) / 256, 256>>>(ei, x, tt);
    k_scanA<<<NB, 1024>>>();
    k_scatter<<<(EE + 255) / 256, 256>>>(ei);

    for (int l = 0; l < 2; l++) {
        k_aggr<<<(NN * 32 + 255) / 256, 256>>>(x, l);
        k_gemm1<<<(NN + 63) / 64, 256, smem1>>>(W1 + (size_t)l * CC * CH2,
                                                b1 + l * CH2, l);
        k_gemm2<<<(NN + 63) / 64, 256, smem2>>>(W2 + (size_t)l * CH2 * CC, b2 + l * CC,
                                                gm + l * CH2, bt + l * CH2, tt, l,
                                                out, l == 1);
    }
}